// round 12
// baseline (speedup 1.0000x reference)
#include <cuda_runtime.h>
#include <cuda_fp16.h>
#include <cstdint>

// ============================================================================
// out[n,c,hw] = sum_k g[(c-k)&255] * act[n,k,hw]   (circulant inverse GEMM)
// SINGLE fused kernel: per-CTA inline prep (27-tap forward DFT + Hermitian
// 128-term IDFT, overlapped with the staging LDG burst), fp16 mma.sync
// m16n8k16 (fp32 accum), liveness-masked A-blocks, barrier-free compute,
// early per-mt output stores.
// CTA: 256c x 64hw, 256 threads (8 warps = 4M x 2N), 2 CTAs/SM.
// ============================================================================

__device__ __forceinline__ uint32_t smem_u32(const void* p) {
    uint32_t a;
    asm("{ .reg .u64 t; cvta.to.shared.u64 t, %1; cvt.u32.u64 %0, t; }"
        : "=r"(a) : "l"(p));
    return a;
}
__device__ __forceinline__ void ldsm_x4(uint32_t* r, uint32_t addr) {
    asm volatile("ldmatrix.sync.aligned.m8n8.x4.shared.b16 {%0,%1,%2,%3}, [%4];"
                 : "=r"(r[0]), "=r"(r[1]), "=r"(r[2]), "=r"(r[3]) : "r"(addr));
}
__device__ __forceinline__ void ldsm_x4_t(uint32_t* r, uint32_t addr) {
    asm volatile("ldmatrix.sync.aligned.m8n8.x4.trans.shared.b16 {%0,%1,%2,%3}, [%4];"
                 : "=r"(r[0]), "=r"(r[1]), "=r"(r[2]), "=r"(r[3]) : "r"(addr));
}
__device__ __forceinline__ void mma16816(float* d, const uint32_t* a,
                                         const uint32_t* b) {
    asm volatile(
        "mma.sync.aligned.m16n8k16.row.col.f32.f16.f16.f32 "
        "{%0,%1,%2,%3},{%4,%5,%6,%7},{%8,%9},{%0,%1,%2,%3};"
        : "+f"(d[0]), "+f"(d[1]), "+f"(d[2]), "+f"(d[3])
        : "r"(a[0]), "r"(a[1]), "r"(a[2]), "r"(a[3]), "r"(b[0]), "r"(b[1]));
}

// SMEM layout
static constexpr uint32_t A_PITCH = 80;    // 32 fp16 (64B) + 16B pad
static constexpr uint32_t B_PITCH = 144;   // 64 fp16 (128B) + 16B pad
static constexpr uint32_t OFF_A   = 0;                  // 256*80 = 20480
static constexpr uint32_t OFF_B   = 20480;              // 8 chunk buffers
static constexpr uint32_t B_BUF   = 32 * B_PITCH;       // 4608
static constexpr uint32_t SMEM_BYTES = 20480 + 8 * B_BUF;  // 57344
// prep scratch aliases the B region (dead before any staging STS)
static constexpr uint32_t SC_TWC = OFF_B;
static constexpr uint32_t SC_TWS = OFF_B + 1024;
static constexpr uint32_t SC_GRE = OFF_B + 2048;
static constexpr uint32_t SC_GIM = OFF_B + 3072;
static constexpr uint32_t SC_GS  = OFF_B + 4096;

__global__ __launch_bounds__(256, 2)
void fused_toeplitz_kernel(const float* __restrict__ act,
                           const float* __restrict__ filt,
                           float* __restrict__ out) {
    extern __shared__ __align__(128) char smem[];
    const uint32_t sb = smem_u32(smem);
    const int tid = threadIdx.x;
    const int lid = tid & 31;
    const int wid = tid >> 5;
    const int warp_m = wid >> 1;   // 0..3 -> 64 c each
    const int warp_n = wid & 1;    // 0..1 -> 32 hw each
    const int hw0 = blockIdx.x * 64;
    const int n   = blockIdx.y;

    const float* actn = act + (size_t)n * (256 * 4096);
    float*       outn = out + (size_t)n * (256 * 4096);

    // ---- 1. Issue ALL staging LDGs first (max MLP; prep hides in latency) --
    const int cr = tid >> 3;          // k row 0..31
    const int cc = tid & 7;           // 8-float col 0..7
    const float* gsrc = &actn[(size_t)cr * 4096 + hw0 + cc * 8];
    float4 v0[8], v1[8];
#pragma unroll
    for (int q = 0; q < 8; ++q) {
        v0[q] = *(const float4*)(gsrc + (size_t)q * 32 * 4096);
        v1[q] = *(const float4*)(gsrc + (size_t)q * 32 * 4096 + 4);
    }

    // ---- 2. Inline prep: g = IDFT(1/DFT(delta - padded_rolled_ricker)) ----
    float* twc = (float*)(smem + SC_TWC);
    float* tws = (float*)(smem + SC_TWS);
    float* gre = (float*)(smem + SC_GRE);
    float* gim = (float*)(smem + SC_GIM);
    float* gs  = (float*)(smem + SC_GS);
    {
        float s, c;
        sincospif(-(float)tid / 128.0f, &s, &c);
        twc[tid] = c;
        tws[tid] = s;
    }
    __syncthreads();
    {
        // kv[(243+i)&255] = filt[i]; Mhat[t] = 1 - sum_i filt[i]*tw[t*(243+i)]
        float re = 1.0f, im = 0.0f;
#pragma unroll
        for (int i = 0; i < 27; ++i) {
            float f = __ldg(&filt[i]);
            int idx = (tid * (243 + i)) & 255;
            re = fmaf(-f, twc[idx], re);
            im = fmaf(-f, tws[idx], im);
        }
        float inv = 1.0f / (re * re + im * im);
        gre[tid] = re * inv;
        gim[tid] = -im * inv;
    }
    __syncthreads();
    {
        // Hermitian IDFT: g[t] = (G0 + G128*cos(pi t) + 2*sum_{q=1..127}..)/256
        float a = gre[0] + gre[128] * twc[(tid * 128) & 255];
        for (int q = 1; q < 128; ++q) {
            int idx = (tid * q) & 255;
            a = fmaf(2.0f * gre[q], twc[idx], a);
            a = fmaf(2.0f * gim[q], tws[idx], a);
        }
        gs[tid] = a * (1.0f / 256.0f);
    }
    __syncthreads();

    // ---- 3. A table (row tid) + liveness mask ------------------------------
#pragma unroll
    for (int kk2 = 0; kk2 < 16; ++kk2) {
        float lo = gs[(tid - 2 * kk2) & 255];
        float hi = gs[(tid - 2 * kk2 - 1) & 255];
        __half2 h = __floats2half2_rn(lo, hi);
        *(uint32_t*)(smem + OFF_A + (uint32_t)tid * A_PITCH + kk2 * 4) =
            *(uint32_t*)&h;
    }
    uint32_t mask;
    {
        float mx = 0.0f;
        if (lid < 16) {
            for (int d = 0; d < 47; ++d)
                mx = fmaxf(mx, fabsf(gs[(16 * lid - 31 + d) & 255]));
        }
        mask = __ballot_sync(0xFFFFFFFFu, (lid < 16) && (mx > 1e-5f)) & 0xFFFFu;
    }
    __syncthreads();   // prep scratch reads done -> B staging may overwrite

    // ---- 4. Stage all 8 chunks: cvt fp32->fp16, STS ------------------------
    const uint32_t sts = sb + OFF_B + (uint32_t)cr * B_PITCH + (uint32_t)cc * 16;
#pragma unroll
    for (int q = 0; q < 8; ++q) {
        __half2 h0 = __floats2half2_rn(v0[q].x, v0[q].y);
        __half2 h1 = __floats2half2_rn(v0[q].z, v0[q].w);
        __half2 h2 = __floats2half2_rn(v1[q].x, v1[q].y);
        __half2 h3 = __floats2half2_rn(v1[q].z, v1[q].w);
        asm volatile("st.shared.v4.b32 [%0], {%1,%2,%3,%4};"
                     :: "r"(sts + (uint32_t)q * B_BUF),
                        "r"(*(uint32_t*)&h0), "r"(*(uint32_t*)&h1),
                        "r"(*(uint32_t*)&h2), "r"(*(uint32_t*)&h3) : "memory");
    }
    __syncthreads();   // A table + all B chunks visible

    // Per-mt last alive chunk (early-store point)
    int last_j[4];
#pragma unroll
    for (int mt = 0; mt < 4; ++mt) {
        last_j[mt] = 0;
#pragma unroll
        for (int j = 0; j < 8; ++j)
            if ((mask >> ((warp_m * 4 + mt + 32 - 2 * j) & 15)) & 1) last_j[mt] = j;
    }

    // ---- 5. Barrier-free masked compute + early stores ---------------------
    float acc[4][4][4] = {};

#pragma unroll
    for (int j = 0; j < 8; ++j) {
        int al[4];
        int any = 0;
#pragma unroll
        for (int mt = 0; mt < 4; ++mt) {
            al[mt] = (mask >> ((warp_m * 4 + mt + 32 - 2 * j) & 15)) & 1;
            any |= al[mt];
        }

        if (any) {
            const uint32_t bbase = sb + OFF_B + (uint32_t)j * B_BUF;
#pragma unroll
            for (int step = 0; step < 2; ++step) {
                uint32_t brow = (uint32_t)(step * 16 + (lid & 15));
                uint32_t Bf[2][4];
#pragma unroll
                for (int bh = 0; bh < 2; ++bh) {
                    uint32_t bcol = (uint32_t)(warp_n * 32 + bh * 16 + ((lid >> 4) << 3));
                    ldsm_x4_t(Bf[bh], bbase + brow * B_PITCH + bcol * 2);
                }
#pragma unroll
                for (int mt = 0; mt < 4; ++mt) {
                    if (!al[mt]) continue;
                    int sbase = ((warp_m * 64 + mt * 16) - j * 32) & 255;
                    uint32_t arow = (uint32_t)(sbase + (lid & 15));
                    uint32_t acol = (uint32_t)(step * 32 + ((lid >> 4) << 4));
                    uint32_t Af[4];
                    ldsm_x4(Af, sb + OFF_A + arow * A_PITCH + acol);
                    mma16816(acc[mt][0], Af, Bf[0]);
                    mma16816(acc[mt][1], Af, Bf[0] + 2);
                    mma16816(acc[mt][2], Af, Bf[1]);
                    mma16816(acc[mt][3], Af, Bf[1] + 2);
                }
            }
        }

        // Early stores: tiles finalized at this chunk
#pragma unroll
        for (int mt = 0; mt < 4; ++mt) {
            if (last_j[mt] != j) continue;
            int c = warp_m * 64 + mt * 16 + (lid >> 2);
#pragma unroll
            for (int nq = 0; nq < 4; ++nq) {
                int col = hw0 + warp_n * 32 + nq * 8 + (lid & 3) * 2;
                *(float2*)&outn[(size_t)c * 4096 + col] =
                    make_float2(acc[mt][nq][0], acc[mt][nq][1]);
                *(float2*)&outn[(size_t)(c + 8) * 4096 + col] =
                    make_float2(acc[mt][nq][2], acc[mt][nq][3]);
            }
        }
    }
}

// ---------------------------------------------------------------------------
extern "C" void kernel_launch(void* const* d_in, const int* in_sizes, int n_in,
                              void* d_out, int out_size) {
    const float* act;
    const float* filt;
    if (n_in >= 2 && in_sizes[0] == 27) {
        filt = (const float*)d_in[0];
        act  = (const float*)d_in[1];
    } else {
        act  = (const float*)d_in[0];
        filt = (const float*)d_in[1];
    }

    cudaFuncSetAttribute(fused_toeplitz_kernel,
                         cudaFuncAttributeMaxDynamicSharedMemorySize, SMEM_BYTES);

    dim3 grid(4096 / 64, 32);   // (64, 32) = 2048 CTAs
    fused_toeplitz_kernel<<<grid, 256, SMEM_BYTES>>>(act, filt, (float*)d_out);
}

// round 13
// speedup vs baseline: 1.7845x; 1.7845x over previous
#include <cuda_runtime.h>
#include <cuda_fp16.h>
#include <cstdint>

// ============================================================================
// out[n,c,hw] = sum_k g[(c-k)&255] * act[n,k,hw]   (circulant inverse GEMM)
// fp16 mma.sync m16n8k16 (fp32 accum). g has narrow effective support, so
// 16c x 32k A-blocks with max|g| < 1e-5 are skipped (runtime 16-bit mask from
// prep). All 8 B chunks staged to SMEM up front -> barrier-free compute phase.
// CTA: 256c x 64hw, 256 threads (8 warps = 4M x 2N), 2 CTAs/SM.
// Prep kernel: 27-tap forward DFT + Hermitian IDFT + ballot mask (~1-2us).
// ============================================================================

__device__ __align__(16) __half aext_g[256 * 32];
__device__ uint32_t g_mask;

// ---------------------------------------------------------------------------
// Prep: g = IDFT(1/DFT(delta - padded_rolled_ricker)); fp16 circulant table
// + per-block liveness mask. Fast: 27-tap forward, Hermitian IDFT, ballot mask.
// ---------------------------------------------------------------------------
__global__ void prep_kernel(const float* __restrict__ filt) {
    __shared__ float f_s[27];
    __shared__ float twc[256];
    __shared__ float tws[256];
    __shared__ float gre[256];
    __shared__ float gim[256];
    __shared__ float g_s[256];

    int t = threadIdx.x;
    if (t < 27) f_s[t] = filt[t];

    float s, c;
    sincospif(-(float)t / 128.0f, &s, &c);
    twc[t] = c;
    tws[t] = s;
    __syncthreads();

    // m[d] = delta[d] - kv[d]; kv[(243+i)&255] = filt[i] (27 taps).
    // Mhat[t] = 1 - sum_i filt[i] * tw[(t*(243+i)) & 255]
    float re = 1.0f, im = 0.0f;
#pragma unroll
    for (int i = 0; i < 27; ++i) {
        int idx = (t * (243 + i)) & 255;
        re = fmaf(-f_s[i], twc[idx], re);
        im = fmaf(-f_s[i], tws[idx], im);
    }
    float inv = 1.0f / (re * re + im * im);
    gre[t] = re * inv;
    gim[t] = -im * inv;
    __syncthreads();

    // Hermitian IDFT: g[t] = (G0 + G128*(-1)^t + 2*sum_{q=1..127} Re{Gq e^{+i..}})/256
    {
        float a = gre[0] + gre[128] * twc[(t * 128) & 255];
        for (int q = 1; q < 128; ++q) {
            int idx = (t * q) & 255;
            a = fmaf(2.0f * gre[q], twc[idx], a);
            a = fmaf(2.0f * gim[q], tws[idx], a);
        }
        g_s[t] = a * (1.0f / 256.0f);
    }
    __syncthreads();

    for (int kk = 0; kk < 32; ++kk)
        aext_g[t * 32 + kk] = __float2half_rn(g_s[(t - kk) & 255]);

    // Block liveness via ballot: block b covers g indices [16b-31, 16b+15].
    if (t < 32) {
        float mx = 0.0f;
        if (t < 16) {
#pragma unroll 1
            for (int d = 0; d < 47; ++d)
                mx = fmaxf(mx, fabsf(g_s[(16 * t - 31 + d) & 255]));
        }
        uint32_t m = __ballot_sync(0xFFFFFFFFu, (t < 16) && (mx > 1e-5f)) & 0xFFFFu;
        if (t == 0) g_mask = m;
    }
}

// ---------------------------------------------------------------------------
// PTX helpers (base PTX: ldmatrix + mma.sync, sm_80 features)
// ---------------------------------------------------------------------------
__device__ __forceinline__ uint32_t smem_u32(const void* p) {
    uint32_t a;
    asm("{ .reg .u64 t; cvta.to.shared.u64 t, %1; cvt.u32.u64 %0, t; }"
        : "=r"(a) : "l"(p));
    return a;
}
__device__ __forceinline__ void ldsm_x4(uint32_t* r, uint32_t addr) {
    asm volatile("ldmatrix.sync.aligned.m8n8.x4.shared.b16 {%0,%1,%2,%3}, [%4];"
                 : "=r"(r[0]), "=r"(r[1]), "=r"(r[2]), "=r"(r[3]) : "r"(addr));
}
__device__ __forceinline__ void ldsm_x4_t(uint32_t* r, uint32_t addr) {
    asm volatile("ldmatrix.sync.aligned.m8n8.x4.trans.shared.b16 {%0,%1,%2,%3}, [%4];"
                 : "=r"(r[0]), "=r"(r[1]), "=r"(r[2]), "=r"(r[3]) : "r"(addr));
}
__device__ __forceinline__ void mma16816(float* d, const uint32_t* a,
                                         const uint32_t* b) {
    asm volatile(
        "mma.sync.aligned.m16n8k16.row.col.f32.f16.f16.f32 "
        "{%0,%1,%2,%3},{%4,%5,%6,%7},{%8,%9},{%0,%1,%2,%3};"
        : "+f"(d[0]), "+f"(d[1]), "+f"(d[2]), "+f"(d[3])
        : "r"(a[0]), "r"(a[1]), "r"(a[2]), "r"(a[3]), "r"(b[0]), "r"(b[1]));
}

// SMEM layout
static constexpr uint32_t A_PITCH = 80;    // 32 fp16 (64B) + 16B pad
static constexpr uint32_t B_PITCH = 144;   // 64 fp16 (128B) + 16B pad
static constexpr uint32_t OFF_A   = 0;                  // 256*80 = 20480
static constexpr uint32_t OFF_B   = 20480;              // 8 chunk buffers
static constexpr uint32_t B_BUF   = 32 * B_PITCH;       // 4608
static constexpr uint32_t SMEM_BYTES = 20480 + 8 * B_BUF;  // 57344

__global__ __launch_bounds__(256, 2)
void mma_toeplitz_kernel(const float* __restrict__ act, float* __restrict__ out) {
    extern __shared__ __align__(128) char smem[];
    const uint32_t sb = smem_u32(smem);
    const int tid = threadIdx.x;
    const int lid = tid & 31;
    const int wid = tid >> 5;
    const int warp_m = wid >> 1;   // 0..3 -> 64 c each
    const int warp_n = wid & 1;    // 0..1 -> 32 hw each
    const int hw0 = blockIdx.x * 64;
    const int n   = blockIdx.y;

    const float* actn = act + (size_t)n * (256 * 4096);
    float*       outn = out + (size_t)n * (256 * 4096);

    const uint32_t mask = g_mask;

    // Copy circulant A table gmem -> smem (64B rows -> pitch 80)
    {
        const float4* src = (const float4*)aext_g;
#pragma unroll
        for (int l = 0; l < 4; ++l) {
            int i = tid + l * 256;
            uint32_t dst = (uint32_t)(i >> 2) * A_PITCH + (uint32_t)(i & 3) * 16;
            *(float4*)(smem + OFF_A + dst) = src[i];
        }
    }

    // ---- Stage ALL 8 chunks: LDG fp32 -> cvt -> STS fp16 -----------------
    // Thread owns k row cr, hw cols [cc*8, cc*8+8): 2 float4 loads, 1 STS.128.
    {
        const int cr = tid >> 3;          // 0..31
        const int cc = tid & 7;           // 0..7
        const float* gsrc = &actn[(size_t)cr * 4096 + hw0 + cc * 8];
        const uint32_t sts = sb + OFF_B + (uint32_t)cr * B_PITCH + (uint32_t)cc * 16;
#pragma unroll
        for (int q = 0; q < 8; q += 2) {
            float4 a0 = *(const float4*)(gsrc + (size_t)q * 32 * 4096);
            float4 a1 = *(const float4*)(gsrc + (size_t)q * 32 * 4096 + 4);
            float4 b0 = *(const float4*)(gsrc + (size_t)(q + 1) * 32 * 4096);
            float4 b1 = *(const float4*)(gsrc + (size_t)(q + 1) * 32 * 4096 + 4);
            __half2 h0 = __floats2half2_rn(a0.x, a0.y);
            __half2 h1 = __floats2half2_rn(a0.z, a0.w);
            __half2 h2 = __floats2half2_rn(a1.x, a1.y);
            __half2 h3 = __floats2half2_rn(a1.z, a1.w);
            asm volatile("st.shared.v4.b32 [%0], {%1,%2,%3,%4};"
                         :: "r"(sts + (uint32_t)q * B_BUF),
                            "r"(*(uint32_t*)&h0), "r"(*(uint32_t*)&h1),
                            "r"(*(uint32_t*)&h2), "r"(*(uint32_t*)&h3) : "memory");
            __half2 g0 = __floats2half2_rn(b0.x, b0.y);
            __half2 g1 = __floats2half2_rn(b0.z, b0.w);
            __half2 g2 = __floats2half2_rn(b1.x, b1.y);
            __half2 g3 = __floats2half2_rn(b1.z, b1.w);
            asm volatile("st.shared.v4.b32 [%0], {%1,%2,%3,%4};"
                         :: "r"(sts + (uint32_t)(q + 1) * B_BUF),
                            "r"(*(uint32_t*)&g0), "r"(*(uint32_t*)&g1),
                            "r"(*(uint32_t*)&g2), "r"(*(uint32_t*)&g3) : "memory");
        }
    }
    __syncthreads();   // A table + all B chunks visible

    // ---- Barrier-free compute: skip dead A blocks --------------------------
    float acc[4][4][4] = {};

#pragma unroll
    for (int j = 0; j < 8; ++j) {
        int al[4];
        int any = 0;
#pragma unroll
        for (int mt = 0; mt < 4; ++mt) {
            al[mt] = (mask >> ((warp_m * 4 + mt + 32 - 2 * j) & 15)) & 1;
            any |= al[mt];
        }
        if (!any) continue;

        const uint32_t bbase = sb + OFF_B + (uint32_t)j * B_BUF;
#pragma unroll
        for (int step = 0; step < 2; ++step) {
            uint32_t brow = (uint32_t)(step * 16 + (lid & 15));
            uint32_t Bf[2][4];
#pragma unroll
            for (int bh = 0; bh < 2; ++bh) {
                uint32_t bcol = (uint32_t)(warp_n * 32 + bh * 16 + ((lid >> 4) << 3));
                ldsm_x4_t(Bf[bh], bbase + brow * B_PITCH + bcol * 2);
            }
#pragma unroll
            for (int mt = 0; mt < 4; ++mt) {
                if (!al[mt]) continue;
                int sbase = ((warp_m * 64 + mt * 16) - j * 32) & 255;
                uint32_t arow = (uint32_t)(sbase + (lid & 15));
                uint32_t acol = (uint32_t)(step * 32 + ((lid >> 4) << 4));
                uint32_t Af[4];
                ldsm_x4(Af, sb + OFF_A + arow * A_PITCH + acol);
                mma16816(acc[mt][0], Af, Bf[0]);
                mma16816(acc[mt][1], Af, Bf[0] + 2);
                mma16816(acc[mt][2], Af, Bf[1]);
                mma16816(acc[mt][3], Af, Bf[1] + 2);
            }
        }
    }

    // Epilogue: direct stores (lane quads cover 32B sectors)
#pragma unroll
    for (int mt = 0; mt < 4; ++mt) {
        int c = warp_m * 64 + mt * 16 + (lid >> 2);
#pragma unroll
        for (int nq = 0; nq < 4; ++nq) {
            int col = hw0 + warp_n * 32 + nq * 8 + (lid & 3) * 2;
            *(float2*)&outn[(size_t)c * 4096 + col] =
                make_float2(acc[mt][nq][0], acc[mt][nq][1]);
            *(float2*)&outn[(size_t)(c + 8) * 4096 + col] =
                make_float2(acc[mt][nq][2], acc[mt][nq][3]);
        }
    }
}

// ---------------------------------------------------------------------------
extern "C" void kernel_launch(void* const* d_in, const int* in_sizes, int n_in,
                              void* d_out, int out_size) {
    const float* act;
    const float* filt;
    if (n_in >= 2 && in_sizes[0] == 27) {
        filt = (const float*)d_in[0];
        act  = (const float*)d_in[1];
    } else {
        act  = (const float*)d_in[0];
        filt = (const float*)d_in[1];
    }

    cudaFuncSetAttribute(mma_toeplitz_kernel,
                         cudaFuncAttributeMaxDynamicSharedMemorySize, SMEM_BYTES);

    prep_kernel<<<1, 256>>>(filt);

    dim3 grid(4096 / 64, 32);   // (64, 32) = 2048 CTAs
    mma_toeplitz_kernel<<<grid, 256, SMEM_BYTES>>>(act, (float*)d_out);
}